// round 12
// baseline (speedup 1.0000x reference)
#include <cuda_runtime.h>
#include <cuda_bf16.h>
#include <math.h>

#define T_STEPS 2048
#define L 1024
#define CSZ 16                 // cluster size (nonportable, opt-in)
#define CPC (L / CSZ)          // 64 columns per CTA
#define NT 512                 // 16 warps; warp w owns 4 cols
#define NWP 16
#define TX_BYTES 2048u         // bytes landing in each CTA's sa[x] per step

// Packed exp(transfer): g_Epack[k][lane][col] = uint2{ bf16x2(E[i0],E[i0+1]),
// bf16x2(E[i0+2],E[i0+3]) }[col], i0 = 4*lane + 128*k.
__device__ uint2 g_Epack[8][32][L];   // 2 MB

// ---------------------------------------------------------------------------
// helpers
// ---------------------------------------------------------------------------
__device__ __forceinline__ unsigned smem_u32(const void* p) {
    unsigned a;
    asm("{ .reg .u64 t; cvta.to.shared.u64 t, %1; cvt.u32.u64 %0, t; }"
        : "=r"(a) : "l"(p));
    return a;
}
__device__ __forceinline__ void st_cluster_f32(unsigned laddr, unsigned rank, float v) {
    unsigned ra;
    asm volatile("mapa.shared::cluster.u32 %0, %1, %2;" : "=r"(ra) : "r"(laddr), "r"(rank));
    asm volatile("st.shared::cluster.f32 [%0], %1;" :: "r"(ra), "f"(v) : "memory");
}
__device__ __forceinline__ void st_async_u64(unsigned laddr, unsigned lmbar,
                                             unsigned rank, unsigned long long v) {
    unsigned ra, rm;
    asm volatile("mapa.shared::cluster.u32 %0, %1, %2;" : "=r"(ra) : "r"(laddr), "r"(rank));
    asm volatile("mapa.shared::cluster.u32 %0, %1, %2;" : "=r"(rm) : "r"(lmbar), "r"(rank));
    asm volatile("st.async.shared::cluster.mbarrier::complete_tx::bytes.b64 [%0], %1, [%2];"
                 :: "r"(ra), "l"(v), "r"(rm) : "memory");
}
__device__ __forceinline__ void mbar_init(unsigned mbar, unsigned count) {
    asm volatile("mbarrier.init.shared.b64 [%0], %1;" :: "r"(mbar), "r"(count) : "memory");
}
__device__ __forceinline__ void mbar_arm(unsigned mbar, unsigned bytes) {
    asm volatile("mbarrier.arrive.expect_tx.shared.b64 _, [%0], %1;"
                 :: "r"(mbar), "r"(bytes) : "memory");
}
__device__ __forceinline__ void mbar_wait(unsigned mbar, unsigned parity) {
    asm volatile(
        "{\n\t.reg .pred P;\n\t"
        "WAIT_%=:\n\t"
        "mbarrier.try_wait.parity.acquire.cluster.shared::cta.b64 P, [%0], %1;\n\t"
        "@!P bra WAIT_%=;\n\t"
        "}" :: "r"(mbar), "r"(parity) : "memory");
}
#define CLUSTER_SYNC() do { \
    asm volatile("barrier.cluster.arrive.aligned;" ::: "memory"); \
    asm volatile("barrier.cluster.wait.aligned;"   ::: "memory"); } while (0)

__device__ __forceinline__ __nv_bfloat162 u2b(unsigned u) {
    return *reinterpret_cast<__nv_bfloat162*>(&u);
}

// ---------------------------------------------------------------------------
// Prep: build g_Epack (coalesced)
// ---------------------------------------------------------------------------
__global__ void crf_prep_E(const float* __restrict__ transfer) {
    int k = blockIdx.x >> 5, l = blockIdx.x & 31;
    int col = threadIdx.x;
    int i0 = 4 * l + 128 * k;
    float e0 = __expf(transfer[(i0 + 0) * L + col]);
    float e1 = __expf(transfer[(i0 + 1) * L + col]);
    float e2 = __expf(transfer[(i0 + 2) * L + col]);
    float e3 = __expf(transfer[(i0 + 3) * L + col]);
    __nv_bfloat162 p0 = __floats2bfloat162_rn(e0, e1);
    __nv_bfloat162 p1 = __floats2bfloat162_rn(e2, e3);
    g_Epack[k][l][col] = make_uint2(*reinterpret_cast<unsigned*>(&p0),
                                    *reinterpret_cast<unsigned*>(&p1));
}

// ---------------------------------------------------------------------------
// Cluster forward kernel: 16 warps x 4 cols, HFMA2 matvec (E in regs),
// fp32 short-fold reduction, b64 gather-push (1 st.async warp-instr/warp),
// mbarrier tx counting. No per-step block barriers.
// ---------------------------------------------------------------------------
__global__ void __launch_bounds__(NT, 1)
crf_cluster_kernel(const float* __restrict__ feats,
                   const float* __restrict__ transfer,
                   const int*   __restrict__ target,
                   float* __restrict__ out) {
    __shared__ __nv_bfloat16 sa[2][L];                 // 4 KB double-buffered state
    __shared__ __align__(8) unsigned long long smbar[2];
    __shared__ float sgold[CSZ];
    __shared__ float sred[NWP];

    const int tid  = threadIdx.x;
    const int w    = tid >> 5;
    const int lane = tid & 31;
    const int bit4 = (lane >> 4) & 1;
    const int bit3 = (lane >> 3) & 1;
    const int q    = 2 * bit4 + bit3;      // this lane's owned column offset
    unsigned rank;
    asm("mov.u32 %0, %%cluster_ctarank;" : "=r"(rank));
    const int col0 = rank * CPC;
    const int wcol = col0 + w * 4;         // warp's 4-column base (global)

    const unsigned mb0 = smem_u32(&smbar[0]);
    const unsigned mb1 = smem_u32(&smbar[1]);

    // --- E into registers: E[c][k][p], c in [0,4) ---
    __nv_bfloat162 E[4][8][2];
    #pragma unroll
    for (int k = 0; k < 8; k++) {
        #pragma unroll
        for (int cp = 0; cp < 2; cp++) {
            uint4 t4 = *(const uint4*)&g_Epack[k][lane][wcol + 2 * cp];
            E[2 * cp + 0][k][0] = u2b(t4.x);  E[2 * cp + 0][k][1] = u2b(t4.y);
            E[2 * cp + 1][k][0] = u2b(t4.z);  E[2 * cp + 1][k][1] = u2b(t4.w);
        }
    }

    // --- mbarriers: init + arm both ---
    if (tid == 0) {
        mbar_init(mb0, 1);
        mbar_init(mb1, 1);
        mbar_arm(mb0, TX_BYTES);
        mbar_arm(mb1, TX_BYTES);
    }

    // --- bootstrap a_0 = exp(feats[0]) (identical bits in every CTA) ---
    for (int n = tid; n < L; n += NT)
        sa[0][n] = __float2bfloat16(__expf(feats[n]));

    // --- gold partial for t in [rank*128, (rank+1)*128), pushed to rank 0 ---
    {
        float s = 0.f;
        int tbase = rank * (T_STEPS / CSZ);
        for (int t = tbase + tid; t < tbase + T_STEPS / CSZ; t += NT) {
            int lab = target[t];
            s += feats[t * L + lab];
            if (t < T_STEPS - 1) s += transfer[lab * L + target[t + 1]];
        }
        #pragma unroll
        for (int o = 16; o; o >>= 1) s += __shfl_xor_sync(0xffffffffu, s, o);
        if (lane == 0) sred[w] = s;
        __syncthreads();
        if (tid == 0) {
            float g = 0.f;
            #pragma unroll
            for (int qq = 0; qq < NWP; qq++) g += sred[qq];
            st_cluster_f32(smem_u32(&sgold[rank]), 0, g);
        }
    }
    CLUSTER_SYNC();   // E regs / a_0 / gold / mbarrier init visible cluster-wide

    int K = 0;
    int ph0 = 0, ph1 = 0;
    const __nv_bfloat162 bz = __float2bfloat162_rn(0.f);

    // emission prefetch for this lane's owned column, one step ahead
    float fpre = __ldg(&feats[1 * L + wcol + q]);

    for (int t = 0; t < T_STEPS - 1; t++) {
        const int cur = t & 1, nxt = cur ^ 1;

        float fcur = fpre;
        int tn = (t + 2 < T_STEPS) ? (t + 2) : (T_STEPS - 1);
        fpre = __ldg(&feats[tn * L + wcol + q]);

        // wait for buffer cur to be fully delivered (t=0: local bootstrap)
        if (t > 0) {
            if (cur) { mbar_wait(mb1, ph1); ph1 ^= 1; }
            else     { mbar_wait(mb0, ph0); ph0 ^= 1; }
            if (tid == 0) mbar_arm(cur ? mb1 : mb0, TX_BYTES);
        }

        // consistent rescale exponent from bf16 a_t[0] (identical everywhere)
        unsigned short us = __bfloat16_as_ushort(sa[cur][0]);
        int d = (int)((us >> 7) & 0xFF) - 127;
        K += d;
        float scale = __int_as_float((127 - d) << 23);   // exact 2^-d
        float em = __expf(fcur) * scale;

        // --- matvec: 4 cols/warp, HFMA2 (chains of 8), E in regs ---
        __nv_bfloat162 acc[4][2];
        #pragma unroll
        for (int c = 0; c < 4; c++) { acc[c][0] = bz; acc[c][1] = bz; }
        #pragma unroll
        for (int k = 0; k < 8; k++) {
            uint2 a2 = *(const uint2*)&sa[cur][4 * lane + 128 * k];
            __nv_bfloat162 aA = u2b(a2.x), aB = u2b(a2.y);
            #pragma unroll
            for (int c = 0; c < 4; c++) {
                acc[c][0] = __hfma2(aA, E[c][k][0], acc[c][0]);
                acc[c][1] = __hfma2(aB, E[c][k][1], acc[c][1]);
            }
        }

        // per-col chunk sums -> fp32
        float cs[4];
        #pragma unroll
        for (int c = 0; c < 4; c++) {
            __nv_bfloat162 h = __hadd2(acc[c][0], acc[c][1]);
            cs[c] = __bfloat162float(__low2bfloat16(h)) +
                    __bfloat162float(__high2bfloat16(h));
        }

        // fold 4 -> 2 (xor16), 2 -> 1 (xor8), butterfly xor 4,2,1 : 6 SHFL
        float m0, m1, v;
        {
            float s0 = bit4 ? cs[0] : cs[2], k0 = bit4 ? cs[2] : cs[0];
            float s1 = bit4 ? cs[1] : cs[3], k1 = bit4 ? cs[3] : cs[1];
            m0 = k0 + __shfl_xor_sync(0xffffffffu, s0, 16);
            m1 = k1 + __shfl_xor_sync(0xffffffffu, s1, 16);
        }
        {
            float s0 = bit3 ? m0 : m1, k0 = bit3 ? m1 : m0;
            v = k0 + __shfl_xor_sync(0xffffffffu, s0, 8);
        }
        #pragma unroll
        for (int o = 4; o; o >>= 1) v += __shfl_xor_sync(0xffffffffu, v, o);
        // lane owns col wcol + q, full sum over i

        // finalize in fp32, convert to bf16, gather warp's 4 cols into b64
        unsigned short myh = __bfloat16_as_ushort(__float2bfloat16(v * em));
        unsigned mine16 = (unsigned)myh;
        unsigned oth16  = __shfl_xor_sync(0xffffffffu, mine16, 8);
        unsigned word   = bit3 ? ((mine16 << 16) | oth16)
                               : ((oth16  << 16) | mine16);   // cols (2b4, 2b4+1)
        unsigned otherw = __shfl_xor_sync(0xffffffffu, word, 16);
        unsigned w0 = bit4 ? otherw : word;    // cols 0,1
        unsigned w1 = bit4 ? word   : otherw;  // cols 2,3
        unsigned long long pkt = ((unsigned long long)w1 << 32) | w0;

        // lanes 0..15 each deliver the warp's 4 cols to one rank (1 warp-instr)
        if (lane < CSZ) {
            unsigned la = smem_u32(&sa[nxt][col0 + 4 * w]);
            unsigned lm = nxt ? mb1 : mb0;
            st_async_u64(la, lm, (unsigned)lane, pkt);
        }
    }

    // final buffer fully delivered before exit
    {
        const int last = (T_STEPS - 1) & 1;
        if (last) mbar_wait(mb1, ph1);
        else      mbar_wait(mb0, ph0);
    }

    // --- epilogue: rank 0 computes the loss ---
    if (rank == 0) {
        const int last = (T_STEPS - 1) & 1;
        unsigned a2 = *(const unsigned*)&sa[last][2 * tid];
        __nv_bfloat162 x0 = u2b(a2);
        float s = __bfloat162float(__low2bfloat16(x0)) +
                  __bfloat162float(__high2bfloat16(x0));
        #pragma unroll
        for (int o = 16; o; o >>= 1) s += __shfl_xor_sync(0xffffffffu, s, o);
        if (lane == 0) sred[w] = s;
        __syncthreads();
        if (tid == 0) {
            float tot = 0.f;
            #pragma unroll
            for (int qq = 0; qq < NWP; qq++) tot += sred[qq];
            float gold = 0.f;
            #pragma unroll
            for (int r = 0; r < CSZ; r++) gold += sgold[r];
            double lz = log((double)tot) + (double)K * 0.69314718055994530942;
            out[0] = (float)(lz - (double)gold);
        }
    }
}

extern "C" void kernel_launch(void* const* d_in, const int* in_sizes, int n_in,
                              void* d_out, int out_size) {
    const float* feats    = (const float*)d_in[0];   // [2048, 1024] f32
    const float* transfer = (const float*)d_in[1];   // [1024, 1024] f32
    const int*   target   = (const int*)d_in[2];     // [2048] i32
    float* out = (float*)d_out;

    cudaFuncSetAttribute(crf_cluster_kernel,
                         cudaFuncAttributeNonPortableClusterSizeAllowed, 1);

    crf_prep_E<<<256, 1024>>>(transfer);

    cudaLaunchConfig_t cfg = {};
    cfg.gridDim  = dim3(CSZ, 1, 1);
    cfg.blockDim = dim3(NT, 1, 1);
    cfg.dynamicSmemBytes = 0;
    cfg.stream = 0;
    cudaLaunchAttribute attrs[1];
    attrs[0].id = cudaLaunchAttributeClusterDimension;
    attrs[0].val.clusterDim.x = CSZ;
    attrs[0].val.clusterDim.y = 1;
    attrs[0].val.clusterDim.z = 1;
    cfg.attrs = attrs;
    cfg.numAttrs = 1;

    cudaLaunchKernelEx(&cfg, crf_cluster_kernel, feats, transfer, target, out);
}

// round 13
// speedup vs baseline: 1.2865x; 1.2865x over previous
#include <cuda_runtime.h>
#include <cuda_bf16.h>
#include <math.h>

#define T_STEPS 2048
#define L 1024
#define CSZ 16                 // cluster size (nonportable, opt-in)
#define NT 256                 // 8 warps
#define NW 8
#define HALF_TX 1024u          // tx bytes per half-vector per step per CTA

// Packed exp(transfer): g_Epack[k][lane][col] = uint2{ bf16x2(E[i0],E[i0+1]),
// bf16x2(E[i0+2],E[i0+3]) }[col], i0 = 4*lane + 128*k.
__device__ uint2 g_Epack[8][32][L];   // 2 MB

// ---------------------------------------------------------------------------
// helpers
// ---------------------------------------------------------------------------
__device__ __forceinline__ unsigned smem_u32(const void* p) {
    unsigned a;
    asm("{ .reg .u64 t; cvta.to.shared.u64 t, %1; cvt.u32.u64 %0, t; }"
        : "=r"(a) : "l"(p));
    return a;
}
__device__ __forceinline__ void st_cluster_f32(unsigned laddr, unsigned rank, float v) {
    unsigned ra;
    asm volatile("mapa.shared::cluster.u32 %0, %1, %2;" : "=r"(ra) : "r"(laddr), "r"(rank));
    asm volatile("st.shared::cluster.f32 [%0], %1;" :: "r"(ra), "f"(v) : "memory");
}
__device__ __forceinline__ void st_async_u32(unsigned laddr, unsigned lmbar,
                                             unsigned rank, unsigned v) {
    unsigned ra, rm;
    asm volatile("mapa.shared::cluster.u32 %0, %1, %2;" : "=r"(ra) : "r"(laddr), "r"(rank));
    asm volatile("mapa.shared::cluster.u32 %0, %1, %2;" : "=r"(rm) : "r"(lmbar), "r"(rank));
    asm volatile("st.async.shared::cluster.mbarrier::complete_tx::bytes.b32 [%0], %1, [%2];"
                 :: "r"(ra), "r"(v), "r"(rm) : "memory");
}
__device__ __forceinline__ void mbar_init(unsigned mbar, unsigned count) {
    asm volatile("mbarrier.init.shared.b64 [%0], %1;" :: "r"(mbar), "r"(count) : "memory");
}
__device__ __forceinline__ void mbar_arm(unsigned mbar, unsigned bytes) {
    asm volatile("mbarrier.arrive.expect_tx.shared.b64 _, [%0], %1;"
                 :: "r"(mbar), "r"(bytes) : "memory");
}
__device__ __forceinline__ void mbar_wait(unsigned mbar, unsigned parity) {
    asm volatile(
        "{\n\t.reg .pred P;\n\t"
        "WAIT_%=:\n\t"
        "mbarrier.try_wait.parity.acquire.cluster.shared::cta.b64 P, [%0], %1;\n\t"
        "@!P bra WAIT_%=;\n\t"
        "}" :: "r"(mbar), "r"(parity) : "memory");
}
#define CLUSTER_SYNC() do { \
    asm volatile("barrier.cluster.arrive.aligned;" ::: "memory"); \
    asm volatile("barrier.cluster.wait.aligned;"   ::: "memory"); } while (0)

__device__ __forceinline__ __nv_bfloat162 u2b(unsigned u) {
    return *reinterpret_cast<__nv_bfloat162*>(&u);
}
__device__ __forceinline__ unsigned b2u(__nv_bfloat162 b) {
    return *reinterpret_cast<unsigned*>(&b);
}

// ---------------------------------------------------------------------------
// Prep: build g_Epack (coalesced)
// ---------------------------------------------------------------------------
__global__ void crf_prep_E(const float* __restrict__ transfer) {
    int k = blockIdx.x >> 5, l = blockIdx.x & 31;
    int col = threadIdx.x;
    int i0 = 4 * l + 128 * k;
    float e0 = __expf(transfer[(i0 + 0) * L + col]);
    float e1 = __expf(transfer[(i0 + 1) * L + col]);
    float e2 = __expf(transfer[(i0 + 2) * L + col]);
    float e3 = __expf(transfer[(i0 + 3) * L + col]);
    g_Epack[k][l][col] = make_uint2(b2u(__floats2bfloat162_rn(e0, e1)),
                                    b2u(__floats2bfloat162_rn(e2, e3)));
}

// ---------------------------------------------------------------------------
// Cluster forward kernel — R11 protocol + half-vector pipelining:
//   H0 = cols [0,512) owned by warps 4-7 (hi arbiter priority -> finish first)
//   H1 = cols [512,1024) owned by warps 0-3
//   Per buffer: 2 mbarriers (H0/H1, 1024 tx bytes each). Consumers wait H0,
//   run k=0..3 (i<512) while H1 is in flight, wait H1, run k=4..7.
// ---------------------------------------------------------------------------
__global__ void __launch_bounds__(NT, 1)
crf_cluster_kernel(const float* __restrict__ feats,
                   const float* __restrict__ transfer,
                   const int*   __restrict__ target,
                   float* __restrict__ out) {
    __shared__ __nv_bfloat16 sa[2][L];                  // 4 KB double-buffered state
    __shared__ __align__(8) unsigned long long smbar[4]; // [buf*2 + half]
    __shared__ float sgold[CSZ];
    __shared__ float sred[NW];

    const int tid  = threadIdx.x;
    const int w    = tid >> 5;
    const int lane = tid & 31;
    const int bit4 = (lane >> 4) & 1;
    const int bit3 = (lane >> 3) & 1;
    const int q    = 2 * bit4 + bit3;      // this lane's word (2 cols) in its warp
    unsigned rank;
    asm("mov.u32 %0, %%cluster_ctarank;" : "=r"(rank));

    // warp role: warps 4-7 -> H0 (early half), warps 0-3 -> H1
    const int isH0 = (w >= 4);
    const int wcol = isH0 ? (32 * (int)rank + 8 * (w - 4))
                          : (512 + 32 * (int)rank + 8 * w);   // global col base

    const unsigned mb00 = smem_u32(&smbar[0]);   // buf0, H0
    const unsigned mb01 = smem_u32(&smbar[1]);   // buf0, H1
    const unsigned mb10 = smem_u32(&smbar[2]);   // buf1, H0
    const unsigned mb11 = smem_u32(&smbar[3]);   // buf1, H1

    // --- E into registers: E[c][k][p], c = col offset within warp's 8 ---
    __nv_bfloat162 E[8][8][2];
    #pragma unroll
    for (int k = 0; k < 8; k++) {
        #pragma unroll
        for (int cp = 0; cp < 4; cp++) {
            uint4 t4 = *(const uint4*)&g_Epack[k][lane][wcol + 2 * cp];
            E[2 * cp + 0][k][0] = u2b(t4.x);  E[2 * cp + 0][k][1] = u2b(t4.y);
            E[2 * cp + 1][k][0] = u2b(t4.z);  E[2 * cp + 1][k][1] = u2b(t4.w);
        }
    }

    // --- mbarriers: init + arm all 4 ---
    if (tid == 0) {
        mbar_init(mb00, 1); mbar_init(mb01, 1);
        mbar_init(mb10, 1); mbar_init(mb11, 1);
        mbar_arm(mb00, HALF_TX); mbar_arm(mb01, HALF_TX);
        mbar_arm(mb10, HALF_TX); mbar_arm(mb11, HALF_TX);
    }

    // --- bootstrap a_0 = exp(feats[0]) (identical bits in every CTA) ---
    for (int n = tid; n < L; n += NT)
        sa[0][n] = __float2bfloat16(__expf(feats[n]));

    // --- gold partial for t in [rank*128, (rank+1)*128), pushed to rank 0 ---
    {
        float s = 0.f;
        int tbase = rank * (T_STEPS / CSZ);
        for (int t = tbase + tid; t < tbase + T_STEPS / CSZ; t += NT) {
            int lab = target[t];
            s += feats[t * L + lab];
            if (t < T_STEPS - 1) s += transfer[lab * L + target[t + 1]];
        }
        #pragma unroll
        for (int o = 16; o; o >>= 1) s += __shfl_xor_sync(0xffffffffu, s, o);
        if (lane == 0) sred[w] = s;
        __syncthreads();
        if (tid == 0) {
            float g = 0.f;
            #pragma unroll
            for (int qq = 0; qq < NW; qq++) g += sred[qq];
            st_cluster_f32(smem_u32(&sgold[rank]), 0, g);
        }
    }
    CLUSTER_SYNC();   // E regs / a_0 / gold / mbarrier init visible cluster-wide

    int K = 0;
    int p00 = 0, p01 = 0, p10 = 0, p11 = 0;   // parities [buf][half]
    const __nv_bfloat162 bz = __float2bfloat162_rn(0.f);

    // emission prefetch for this lane's 2 push columns, one step ahead
    float2 fpre = __ldg((const float2*)&feats[1 * L + wcol + 2 * q]);

    for (int t = 0; t < T_STEPS - 1; t++) {
        const int cur = t & 1, nxt = cur ^ 1;

        float2 fcur = fpre;
        int tn = (t + 2 < T_STEPS) ? (t + 2) : (T_STEPS - 1);
        fpre = __ldg((const float2*)&feats[tn * L + wcol + 2 * q]);

        // --- wait H0 of buffer cur (t=0: local bootstrap) ---
        if (t > 0) {
            if (cur) { mbar_wait(mb10, p10); p10 ^= 1;
                       if (tid == 0) mbar_arm(mb10, HALF_TX); }
            else     { mbar_wait(mb00, p00); p00 ^= 1;
                       if (tid == 0) mbar_arm(mb00, HALF_TX); }
        }

        // consistent rescale exponent from bf16 a_t[0] (col 0 is in H0)
        unsigned short us = __bfloat16_as_ushort(sa[cur][0]);
        int d = (int)((us >> 7) & 0xFF) - 127;
        K += d;
        float scale = __int_as_float((127 - d) << 23);   // exact 2^-d
        float emx = __expf(fcur.x) * scale;
        float emy = __expf(fcur.y) * scale;

        // --- matvec part 1: k = 0..3 (i < 512, needs H0 only) ---
        __nv_bfloat162 acc[8][2];
        #pragma unroll
        for (int c = 0; c < 8; c++) { acc[c][0] = bz; acc[c][1] = bz; }
        #pragma unroll
        for (int k = 0; k < 4; k++) {
            uint2 a2 = *(const uint2*)&sa[cur][4 * lane + 128 * k];
            __nv_bfloat162 aA = u2b(a2.x), aB = u2b(a2.y);
            #pragma unroll
            for (int c = 0; c < 8; c++) {
                acc[c][0] = __hfma2(aA, E[c][k][0], acc[c][0]);
                acc[c][1] = __hfma2(aB, E[c][k][1], acc[c][1]);
            }
        }

        // --- wait H1 of buffer cur (overlapped with part-1 compute) ---
        if (t > 0) {
            if (cur) { mbar_wait(mb11, p11); p11 ^= 1;
                       if (tid == 0) mbar_arm(mb11, HALF_TX); }
            else     { mbar_wait(mb01, p01); p01 ^= 1;
                       if (tid == 0) mbar_arm(mb01, HALF_TX); }
        }

        // --- matvec part 2: k = 4..7 (i >= 512) ---
        #pragma unroll
        for (int k = 4; k < 8; k++) {
            uint2 a2 = *(const uint2*)&sa[cur][4 * lane + 128 * k];
            __nv_bfloat162 aA = u2b(a2.x), aB = u2b(a2.y);
            #pragma unroll
            for (int c = 0; c < 8; c++) {
                acc[c][0] = __hfma2(aA, E[c][k][0], acc[c][0]);
                acc[c][1] = __hfma2(aB, E[c][k][1], acc[c][1]);
            }
        }

        // per-col chunk sums -> fp32
        float cs[8];
        #pragma unroll
        for (int c = 0; c < 8; c++) {
            __nv_bfloat162 h = __hadd2(acc[c][0], acc[c][1]);
            cs[c] = __bfloat162float(__low2bfloat16(h)) +
                    __bfloat162float(__high2bfloat16(h));
        }

        // folded reduction: 8 -> 4 (xor16), 4 -> 2 (xor8), butterfly x3
        float n0, n1, n2, n3;
        {
            float s0 = bit4 ? cs[0] : cs[4], k0 = bit4 ? cs[4] : cs[0];
            float s1 = bit4 ? cs[1] : cs[5], k1 = bit4 ? cs[5] : cs[1];
            float s2 = bit4 ? cs[2] : cs[6], k2 = bit4 ? cs[6] : cs[2];
            float s3 = bit4 ? cs[3] : cs[7], k3 = bit4 ? cs[7] : cs[3];
            n0 = k0 + __shfl_xor_sync(0xffffffffu, s0, 16);
            n1 = k1 + __shfl_xor_sync(0xffffffffu, s1, 16);
            n2 = k2 + __shfl_xor_sync(0xffffffffu, s2, 16);
            n3 = k3 + __shfl_xor_sync(0xffffffffu, s3, 16);
        }
        float v0, v1;
        {
            float s0 = bit3 ? n0 : n2, k0 = bit3 ? n2 : n0;
            float s1 = bit3 ? n1 : n3, k1 = bit3 ? n3 : n1;
            v0 = k0 + __shfl_xor_sync(0xffffffffu, s0, 8);
            v1 = k1 + __shfl_xor_sync(0xffffffffu, s1, 8);
        }
        #pragma unroll
        for (int o = 4; o; o >>= 1) {
            v0 += __shfl_xor_sync(0xffffffffu, v0, o);
            v1 += __shfl_xor_sync(0xffffffffu, v1, o);
        }
        // lane owns cols wcol+2q, wcol+2q+1 summed over all i

        unsigned val = b2u(__floats2bfloat162_rn(v0 * emx, v1 * emy));

        // async push to 2 ranks; tx counts into target's half-mbar of buf nxt
        unsigned la = smem_u32(&sa[nxt][wcol + 2 * q]);
        unsigned lm = nxt ? (isH0 ? mb10 : mb11) : (isH0 ? mb00 : mb01);
        unsigned r0 = (unsigned)(lane & 7) * 2;
        st_async_u32(la, lm, r0,     val);
        st_async_u32(la, lm, r0 + 1, val);
    }

    // final buffer (both halves) fully delivered before any CTA may exit
    {
        const int last = (T_STEPS - 1) & 1;
        if (last) { mbar_wait(mb10, p10); mbar_wait(mb11, p11); }
        else      { mbar_wait(mb00, p00); mbar_wait(mb01, p01); }
    }

    // --- epilogue: rank 0 computes the loss ---
    if (rank == 0) {
        const int last = (T_STEPS - 1) & 1;
        uint2 a2 = *(const uint2*)&sa[last][4 * tid];
        __nv_bfloat162 x0 = u2b(a2.x), x1 = u2b(a2.y);
        float s = __bfloat162float(__low2bfloat16(x0)) +
                  __bfloat162float(__high2bfloat16(x0)) +
                  __bfloat162float(__low2bfloat16(x1)) +
                  __bfloat162float(__high2bfloat16(x1));
        #pragma unroll
        for (int o = 16; o; o >>= 1) s += __shfl_xor_sync(0xffffffffu, s, o);
        if (lane == 0) sred[w] = s;
        __syncthreads();
        if (tid == 0) {
            float tot = 0.f;
            #pragma unroll
            for (int qq = 0; qq < NW; qq++) tot += sred[qq];
            float gold = 0.f;
            #pragma unroll
            for (int r = 0; r < CSZ; r++) gold += sgold[r];
            double lz = log((double)tot) + (double)K * 0.69314718055994530942;
            out[0] = (float)(lz - (double)gold);
        }
    }
}

extern "C" void kernel_launch(void* const* d_in, const int* in_sizes, int n_in,
                              void* d_out, int out_size) {
    const float* feats    = (const float*)d_in[0];   // [2048, 1024] f32
    const float* transfer = (const float*)d_in[1];   // [1024, 1024] f32
    const int*   target   = (const int*)d_in[2];     // [2048] i32
    float* out = (float*)d_out;

    cudaFuncSetAttribute(crf_cluster_kernel,
                         cudaFuncAttributeNonPortableClusterSizeAllowed, 1);

    crf_prep_E<<<256, 1024>>>(transfer);

    cudaLaunchConfig_t cfg = {};
    cfg.gridDim  = dim3(CSZ, 1, 1);
    cfg.blockDim = dim3(NT, 1, 1);
    cfg.dynamicSmemBytes = 0;
    cfg.stream = 0;
    cudaLaunchAttribute attrs[1];
    attrs[0].id = cudaLaunchAttributeClusterDimension;
    attrs[0].val.clusterDim.x = CSZ;
    attrs[0].val.clusterDim.y = 1;
    attrs[0].val.clusterDim.z = 1;
    cfg.attrs = attrs;
    cfg.numAttrs = 1;

    cudaLaunchKernelEx(&cfg, crf_cluster_kernel, feats, transfer, target, out);
}

// round 14
// speedup vs baseline: 1.4169x; 1.1014x over previous
#include <cuda_runtime.h>
#include <cuda_bf16.h>
#include <math.h>

#define T_STEPS 2048
#define L 1024
#define CSZ 16                 // cluster size (nonportable, opt-in)
#define CPC (L / CSZ)          // 64 columns per CTA
#define NT 256                 // 8 warps
#define NW 8
#define TX_BYTES 2048u         // bytes landing in each CTA's sa[x] per step

// Packed exp(transfer): g_Epack[k][lane][col] = uint2{ bf16x2(E[i0],E[i0+1]),
// bf16x2(E[i0+2],E[i0+3]) }[col], i0 = 4*lane + 128*k.
__device__ uint2 g_Epack[8][32][L];   // 2 MB

// ---------------------------------------------------------------------------
// helpers
// ---------------------------------------------------------------------------
__device__ __forceinline__ unsigned smem_u32(const void* p) {
    unsigned a;
    asm("{ .reg .u64 t; cvta.to.shared.u64 t, %1; cvt.u32.u64 %0, t; }"
        : "=r"(a) : "l"(p));
    return a;
}
__device__ __forceinline__ unsigned mapa_u32(unsigned laddr, unsigned rank) {
    unsigned ra;
    asm("mapa.shared::cluster.u32 %0, %1, %2;" : "=r"(ra) : "r"(laddr), "r"(rank));
    return ra;
}
__device__ __forceinline__ void st_cluster_f32(unsigned laddr, unsigned rank, float v) {
    unsigned ra = mapa_u32(laddr, rank);
    asm volatile("st.shared::cluster.f32 [%0], %1;" :: "r"(ra), "f"(v) : "memory");
}
// raw async store: remote data addr + remote mbar addr already mapped
__device__ __forceinline__ void st_async_raw(unsigned ra, unsigned rm, unsigned v) {
    asm volatile("st.async.shared::cluster.mbarrier::complete_tx::bytes.b32 [%0], %1, [%2];"
                 :: "r"(ra), "r"(v), "r"(rm) : "memory");
}
__device__ __forceinline__ void mbar_init(unsigned mbar, unsigned count) {
    asm volatile("mbarrier.init.shared.b64 [%0], %1;" :: "r"(mbar), "r"(count) : "memory");
}
__device__ __forceinline__ void mbar_arm(unsigned mbar, unsigned bytes) {
    asm volatile("mbarrier.arrive.expect_tx.shared.b64 _, [%0], %1;"
                 :: "r"(mbar), "r"(bytes) : "memory");
}
__device__ __forceinline__ void mbar_wait(unsigned mbar, unsigned parity) {
    asm volatile(
        "{\n\t.reg .pred P;\n\t"
        "WAIT_%=:\n\t"
        "mbarrier.try_wait.parity.acquire.cluster.shared::cta.b64 P, [%0], %1;\n\t"
        "@!P bra WAIT_%=;\n\t"
        "}" :: "r"(mbar), "r"(parity) : "memory");
}
#define CLUSTER_SYNC() do { \
    asm volatile("barrier.cluster.arrive.aligned;" ::: "memory"); \
    asm volatile("barrier.cluster.wait.aligned;"   ::: "memory"); } while (0)

__device__ __forceinline__ __nv_bfloat162 u2b(unsigned u) {
    return *reinterpret_cast<__nv_bfloat162*>(&u);
}
__device__ __forceinline__ unsigned b2u(__nv_bfloat162 b) {
    return *reinterpret_cast<unsigned*>(&b);
}

// ---------------------------------------------------------------------------
// Prep: build g_Epack (coalesced)
// ---------------------------------------------------------------------------
__global__ void crf_prep_E(const float* __restrict__ transfer) {
    int k = blockIdx.x >> 5, l = blockIdx.x & 31;
    int col = threadIdx.x;
    int i0 = 4 * l + 128 * k;
    float e0 = __expf(transfer[(i0 + 0) * L + col]);
    float e1 = __expf(transfer[(i0 + 1) * L + col]);
    float e2 = __expf(transfer[(i0 + 2) * L + col]);
    float e3 = __expf(transfer[(i0 + 3) * L + col]);
    g_Epack[k][l][col] = make_uint2(b2u(__floats2bfloat162_rn(e0, e1)),
                                    b2u(__floats2bfloat162_rn(e2, e3)));
}

// ---------------------------------------------------------------------------
// Cluster forward kernel — R11 protocol, control path stripped:
// unroll x2 (static buffers), peeled t=0, hoisted mapa, pre-wait MUFU.
// ---------------------------------------------------------------------------
__global__ void __launch_bounds__(NT, 1)
crf_cluster_kernel(const float* __restrict__ feats,
                   const float* __restrict__ transfer,
                   const int*   __restrict__ target,
                   float* __restrict__ out) {
    __shared__ __nv_bfloat16 sa[2][L];                 // 4 KB double-buffered state
    __shared__ __align__(8) unsigned long long smbar[2];
    __shared__ float sgold[CSZ];
    __shared__ float sred[NW];

    const int tid  = threadIdx.x;
    const int w    = tid >> 5;
    const int lane = tid & 31;
    const int bit4 = (lane >> 4) & 1;
    const int bit3 = (lane >> 3) & 1;
    const int q    = 2 * bit4 + bit3;      // this lane's word (2 cols)
    unsigned rank;
    asm("mov.u32 %0, %%cluster_ctarank;" : "=r"(rank));
    const int col0 = rank * CPC;
    const int wcol = col0 + w * 8;         // warp's 8-column base (global)

    const unsigned mb0 = smem_u32(&smbar[0]);
    const unsigned mb1 = smem_u32(&smbar[1]);

    // --- E into registers: E[c][k][p] ---
    __nv_bfloat162 E[8][8][2];
    #pragma unroll
    for (int k = 0; k < 8; k++) {
        #pragma unroll
        for (int cp = 0; cp < 4; cp++) {
            uint4 t4 = *(const uint4*)&g_Epack[k][lane][wcol + 2 * cp];
            E[2 * cp + 0][k][0] = u2b(t4.x);  E[2 * cp + 0][k][1] = u2b(t4.y);
            E[2 * cp + 1][k][0] = u2b(t4.z);  E[2 * cp + 1][k][1] = u2b(t4.w);
        }
    }

    // --- mbarriers: init + arm both ---
    if (tid == 0) {
        mbar_init(mb0, 1);
        mbar_init(mb1, 1);
        mbar_arm(mb0, TX_BYTES);
        mbar_arm(mb1, TX_BYTES);
    }

    // --- hoisted remote addresses (loop-invariant): 2 ranks x 2 buffers ---
    const unsigned r0 = (unsigned)(lane & 7) * 2;
    const unsigned la0 = smem_u32(&sa[0][col0 + 8 * w + 2 * q]);
    const unsigned la1 = smem_u32(&sa[1][col0 + 8 * w + 2 * q]);
    const unsigned RA0a = mapa_u32(la0, r0),     RA0b = mapa_u32(la0, r0 + 1);
    const unsigned RA1a = mapa_u32(la1, r0),     RA1b = mapa_u32(la1, r0 + 1);
    const unsigned RM0a = mapa_u32(mb0, r0),     RM0b = mapa_u32(mb0, r0 + 1);
    const unsigned RM1a = mapa_u32(mb1, r0),     RM1b = mapa_u32(mb1, r0 + 1);

    // --- bootstrap a_0 = exp(feats[0]) (identical bits in every CTA) ---
    for (int n = tid; n < L; n += NT)
        sa[0][n] = __float2bfloat16(__expf(feats[n]));

    // --- gold partial for t in [rank*128, (rank+1)*128), pushed to rank 0 ---
    {
        float s = 0.f;
        int tbase = rank * (T_STEPS / CSZ);
        for (int t = tbase + tid; t < tbase + T_STEPS / CSZ; t += NT) {
            int lab = target[t];
            s += feats[t * L + lab];
            if (t < T_STEPS - 1) s += transfer[lab * L + target[t + 1]];
        }
        #pragma unroll
        for (int o = 16; o; o >>= 1) s += __shfl_xor_sync(0xffffffffu, s, o);
        if (lane == 0) sred[w] = s;
        __syncthreads();
        if (tid == 0) {
            float g = 0.f;
            #pragma unroll
            for (int qq = 0; qq < NW; qq++) g += sred[qq];
            st_cluster_f32(smem_u32(&sgold[rank]), 0, g);
        }
    }
    CLUSTER_SYNC();   // E regs / a_0 / gold / mbarrier init visible cluster-wide

    int K = 0;
    int p0 = 0, p1 = 0;
    const __nv_bfloat162 bz = __float2bfloat162_rn(0.f);

    float2 fpre = __ldg((const float2*)&feats[1 * L + wcol + 2 * q]);

// One step: reads sa[CUR_], pushes into all ranks' sa[NXT_] via st.async.
// DO_WAIT_=0 only for the peeled t=0 (local bootstrap data).
#define STEP_BODY(T_, CUR_, NXT_, MBC_, PC_, RAa_, RAb_, RMa_, RMb_, DO_WAIT_)  \
    do {                                                                        \
        float2 fcur_ = fpre;                                                    \
        int tn_ = ((T_) + 2 < T_STEPS) ? ((T_) + 2) : (T_STEPS - 1);            \
        fpre = __ldg((const float2*)&feats[tn_ * L + wcol + 2 * q]);            \
        float ex_ = __expf(fcur_.x);          /* MUFU before the wait */        \
        float ey_ = __expf(fcur_.y);                                            \
        if (DO_WAIT_) {                                                         \
            mbar_wait(MBC_, PC_); PC_ ^= 1;                                     \
            if (tid == 0) mbar_arm(MBC_, TX_BYTES);                             \
        }                                                                       \
        unsigned short us_ = __bfloat16_as_ushort(sa[CUR_][0]);                 \
        int d_ = (int)((us_ >> 7) & 0xFF) - 127;                                \
        K += d_;                                                                \
        float scale_ = __int_as_float((127 - d_) << 23);                        \
        float emx_ = ex_ * scale_, emy_ = ey_ * scale_;                         \
        __nv_bfloat162 acc_[8][2];                                              \
        _Pragma("unroll")                                                       \
        for (int c = 0; c < 8; c++) { acc_[c][0] = bz; acc_[c][1] = bz; }       \
        _Pragma("unroll")                                                       \
        for (int k = 0; k < 8; k++) {                                           \
            uint2 a2_ = *(const uint2*)&sa[CUR_][4 * lane + 128 * k];           \
            __nv_bfloat162 aA_ = u2b(a2_.x), aB_ = u2b(a2_.y);                  \
            _Pragma("unroll")                                                   \
            for (int c = 0; c < 8; c++) {                                       \
                acc_[c][0] = __hfma2(aA_, E[c][k][0], acc_[c][0]);              \
                acc_[c][1] = __hfma2(aB_, E[c][k][1], acc_[c][1]);              \
            }                                                                   \
        }                                                                       \
        float cs_[8];                                                           \
        _Pragma("unroll")                                                       \
        for (int c = 0; c < 8; c++) {                                           \
            __nv_bfloat162 h_ = __hadd2(acc_[c][0], acc_[c][1]);                \
            cs_[c] = __bfloat162float(__low2bfloat16(h_)) +                     \
                     __bfloat162float(__high2bfloat16(h_));                     \
        }                                                                       \
        float n0_, n1_, n2_, n3_;                                               \
        {                                                                       \
            float s0_ = bit4 ? cs_[0] : cs_[4], k0_ = bit4 ? cs_[4] : cs_[0];   \
            float s1_ = bit4 ? cs_[1] : cs_[5], k1_ = bit4 ? cs_[5] : cs_[1];   \
            float s2_ = bit4 ? cs_[2] : cs_[6], k2_ = bit4 ? cs_[6] : cs_[2];   \
            float s3_ = bit4 ? cs_[3] : cs_[7], k3_ = bit4 ? cs_[7] : cs_[3];   \
            n0_ = k0_ + __shfl_xor_sync(0xffffffffu, s0_, 16);                  \
            n1_ = k1_ + __shfl_xor_sync(0xffffffffu, s1_, 16);                  \
            n2_ = k2_ + __shfl_xor_sync(0xffffffffu, s2_, 16);                  \
            n3_ = k3_ + __shfl_xor_sync(0xffffffffu, s3_, 16);                  \
        }                                                                       \
        float v0_, v1_;                                                         \
        {                                                                       \
            float s0_ = bit3 ? n0_ : n2_, k0_ = bit3 ? n2_ : n0_;               \
            float s1_ = bit3 ? n1_ : n3_, k1_ = bit3 ? n3_ : n1_;               \
            v0_ = k0_ + __shfl_xor_sync(0xffffffffu, s0_, 8);                   \
            v1_ = k1_ + __shfl_xor_sync(0xffffffffu, s1_, 8);                   \
        }                                                                       \
        _Pragma("unroll")                                                       \
        for (int o = 4; o; o >>= 1) {                                           \
            v0_ += __shfl_xor_sync(0xffffffffu, v0_, o);                        \
            v1_ += __shfl_xor_sync(0xffffffffu, v1_, o);                        \
        }                                                                       \
        unsigned val_ = b2u(__floats2bfloat162_rn(v0_ * emx_, v1_ * emy_));     \
        st_async_raw(RAa_, RMa_, val_);                                         \
        st_async_raw(RAb_, RMb_, val_);                                         \
    } while (0)

    // peeled t = 0 : buf0 -> buf1, no wait (local bootstrap)
    STEP_BODY(0, 0, 1, mb0, p0, RA1a, RA1b, RM1a, RM1b, 0);

    // pairs t = 1..2046 (1023 iterations)
    for (int t = 1; t < T_STEPS - 1; t += 2) {
        STEP_BODY(t,     1, 0, mb1, p1, RA0a, RA0b, RM0a, RM0b, 1);
        STEP_BODY(t + 1, 0, 1, mb0, p0, RA1a, RA1b, RM1a, RM1b, 1);
    }
#undef STEP_BODY

    // final buffer (a_{T-1} lives in buf1) fully delivered before exit
    mbar_wait(mb1, p1);

    // --- epilogue: rank 0 computes the loss ---
    if (rank == 0) {
        uint2 a2 = *(const uint2*)&sa[1][4 * tid];
        __nv_bfloat162 x0 = u2b(a2.x), x1 = u2b(a2.y);
        float s = __bfloat162float(__low2bfloat16(x0)) +
                  __bfloat162float(__high2bfloat16(x0)) +
                  __bfloat162float(__low2bfloat16(x1)) +
                  __bfloat162float(__high2bfloat16(x1));
        #pragma unroll
        for (int o = 16; o; o >>= 1) s += __shfl_xor_sync(0xffffffffu, s, o);
        if (lane == 0) sred[w] = s;
        __syncthreads();
        if (tid == 0) {
            float tot = 0.f;
            #pragma unroll
            for (int qq = 0; qq < NW; qq++) tot += sred[qq];
            float gold = 0.f;
            #pragma unroll
            for (int r = 0; r < CSZ; r++) gold += sgold[r];
            double lz = log((double)tot) + (double)K * 0.69314718055994530942;
            out[0] = (float)(lz - (double)gold);
        }
    }
}

extern "C" void kernel_launch(void* const* d_in, const int* in_sizes, int n_in,
                              void* d_out, int out_size) {
    const float* feats    = (const float*)d_in[0];   // [2048, 1024] f32
    const float* transfer = (const float*)d_in[1];   // [1024, 1024] f32
    const int*   target   = (const int*)d_in[2];     // [2048] i32
    float* out = (float*)d_out;

    cudaFuncSetAttribute(crf_cluster_kernel,
                         cudaFuncAttributeNonPortableClusterSizeAllowed, 1);

    crf_prep_E<<<256, 1024>>>(transfer);

    cudaLaunchConfig_t cfg = {};
    cfg.gridDim  = dim3(CSZ, 1, 1);
    cfg.blockDim = dim3(NT, 1, 1);
    cfg.dynamicSmemBytes = 0;
    cfg.stream = 0;
    cudaLaunchAttribute attrs[1];
    attrs[0].id = cudaLaunchAttributeClusterDimension;
    attrs[0].val.clusterDim.x = CSZ;
    attrs[0].val.clusterDim.y = 1;
    attrs[0].val.clusterDim.z = 1;
    cfg.attrs = attrs;
    cfg.numAttrs = 1;

    cudaLaunchKernelEx(&cfg, crf_cluster_kernel, feats, transfer, target, out);
}